// round 2
// baseline (speedup 1.0000x reference)
#include <cuda_runtime.h>

#define BSZ   8
#define NN    20000
#define FIN   256
#define NH    8
#define ND    64
#define EE    160000

#define ROWS_PER_BLOCK 128
#define RPW            16   // rows per warp (8 warps * 16 = 128)

// Scratch (device globals — no allocation allowed)
__device__ float g_u[BSZ * 2 * NH * FIN];          // [b][s][h][f]
__device__ float g_scores[2][BSZ * NN * NH];       // [s][b*N*H + n*H + h]
__device__ int   g_idx_is64;                       // 1 if head/tail are int64

// ---------------------------------------------------------------------------
// f32x2 packed helpers (Blackwell: fma.rn.f32x2 = 2x FFMA throughput)
// ---------------------------------------------------------------------------
__device__ __forceinline__ unsigned long long pk2(float lo, float hi) {
    unsigned long long r;
    asm("mov.b64 %0, {%1, %2};" : "=l"(r) : "f"(lo), "f"(hi));
    return r;
}
__device__ __forceinline__ void upk2(unsigned long long v, float& lo, float& hi) {
    asm("mov.b64 {%0, %1}, %2;" : "=f"(lo), "=f"(hi) : "l"(v));
}
__device__ __forceinline__ void fma2(unsigned long long& d,
                                     unsigned long long a, unsigned long long b) {
    asm("fma.rn.f32x2 %0, %1, %2, %0;" : "+l"(d) : "l"(a), "l"(b));
}

// ---------------------------------------------------------------------------
// K0: sniff index dtype. If int64 (values < 2^31), every odd 32-bit word of
// the buffer is 0. If int32, odd words are random indices (virtually never
// all zero across 1024 samples). Writes g_idx_is64.
// ---------------------------------------------------------------------------
__global__ void k_sniff(const unsigned int* __restrict__ head_words) {
    __shared__ int any_nonzero;
    if (threadIdx.x == 0) any_nonzero = 0;
    __syncthreads();
    // Check odd words 1,3,...,2047 (safe: buffer holds >= 1.28M int32 words)
    for (int i = threadIdx.x; i < 1024; i += blockDim.x) {
        if (head_words[2 * i + 1] != 0u) any_nonzero = 1;
    }
    __syncthreads();
    if (threadIdx.x == 0) g_idx_is64 = any_nonzero ? 0 : 1;
}

// ---------------------------------------------------------------------------
// K1: u[b][s][h][f] = sum_d W[h*64+d][f] * scoring_{s}[b][h][d]
// grid = 128 blocks (b*16 + s*8 + h), block = 256 threads (f)
// ---------------------------------------------------------------------------
__global__ void k_prep(const float* __restrict__ W,
                       const float* __restrict__ src,
                       const float* __restrict__ trg) {
    int blk = blockIdx.x;
    int h = blk & 7;
    int s = (blk >> 3) & 1;
    int b = blk >> 4;
    int f = threadIdx.x;

    __shared__ float sc[ND];
    const float* scp = (s == 0 ? src : trg) + (b * NH + h) * ND;
    if (threadIdx.x < ND) sc[threadIdx.x] = scp[threadIdx.x];
    __syncthreads();

    const float* Wp = W + (h * ND) * FIN + f;
    float acc = 0.f;
#pragma unroll 8
    for (int d = 0; d < ND; d++) acc = fmaf(Wp[d * FIN], sc[d], acc);
    g_u[((b * 2 + s) * NH + h) * FIN + f] = acc;
}

// ---------------------------------------------------------------------------
// K2: scores[s][b][n][h] = sum_f ch[b][n][f] * u[b][s][h][f]
// One warp per row, lane l owns f in {4l..4l+3, 128+4l..128+4l+3}.
// u held entirely in registers; 16 accumulators reduced with a 16-shfl
// butterfly exchange (value index = bit-reversed lane).
// ---------------------------------------------------------------------------
__device__ __forceinline__ int rev4(int x) {
    return ((x & 1) << 3) | ((x & 2) << 1) | ((x & 4) >> 1) | ((x & 8) >> 3);
}

__global__ void __launch_bounds__(256, 1)
k_scores(const float* __restrict__ ch) {
    const int b    = blockIdx.y;
    const int base = blockIdx.x * ROWS_PER_BLOCK;
    const int w    = threadIdx.x >> 5;
    const int lane = threadIdx.x & 31;
    const int f0   = lane * 4;

    // Load loop-invariant u slice into registers: 16 outputs x 4 f32x2 each.
    unsigned long long u[16][4];
    const float* ub = g_u + b * (2 * NH * FIN);
#pragma unroll
    for (int j = 0; j < 16; j++) {
        float4 a = *(const float4*)(ub + j * FIN + f0);
        float4 c = *(const float4*)(ub + j * FIN + 128 + f0);
        u[j][0] = pk2(a.x, a.y);
        u[j][1] = pk2(a.z, a.w);
        u[j][2] = pk2(c.x, c.y);
        u[j][3] = pk2(c.z, c.w);
    }

    const float* chb = ch + (long long)b * NN * FIN;

    // Precompute this lane's output mapping (bit-reversed index).
    const int jout = rev4(lane & 15);
    const int so   = jout >> 3;
    const int ho   = jout & 7;

    // 2-deep software prefetch of row data.
    float4 bufA[2], bufB[2];
#pragma unroll
    for (int p = 0; p < 2; p++) {
        int rr = base + p * 8 + w;
        int rc = rr < NN ? rr : NN - 1;
        bufA[p] = *(const float4*)(chb + (long long)rc * FIN + f0);
        bufB[p] = *(const float4*)(chb + (long long)rc * FIN + 128 + f0);
    }

#pragma unroll 2
    for (int r = 0; r < RPW; r++) {
        float4 a = bufA[r & 1];
        float4 c = bufB[r & 1];
        if (r + 2 < RPW) {
            int rr = base + (r + 2) * 8 + w;
            int rc = rr < NN ? rr : NN - 1;
            bufA[r & 1] = *(const float4*)(chb + (long long)rc * FIN + f0);
            bufB[r & 1] = *(const float4*)(chb + (long long)rc * FIN + 128 + f0);
        }

        unsigned long long p0 = pk2(a.x, a.y);
        unsigned long long p1 = pk2(a.z, a.w);
        unsigned long long p2 = pk2(c.x, c.y);
        unsigned long long p3 = pk2(c.z, c.w);

        float v[16];
#pragma unroll
        for (int j = 0; j < 16; j++) {
            unsigned long long acc = 0ull;  // (+0.0f, +0.0f)
            fma2(acc, p0, u[j][0]);
            fma2(acc, p1, u[j][1]);
            fma2(acc, p2, u[j][2]);
            fma2(acc, p3, u[j][3]);
            float lo, hi;
            upk2(acc, lo, hi);
            v[j] = lo + hi;
        }

        // Butterfly exchange-reduce: 16 values across 32 lanes in 16 shfls.
#pragma unroll
        for (int st = 0; st < 4; st++) {
            const int half = 8 >> st;
            const bool up = (lane >> st) & 1;
#pragma unroll
            for (int i = 0; i < half; i++) {
                float send  = up ? v[i] : v[i + half];
                float other = __shfl_xor_sync(0xffffffffu, send, 1 << st);
                v[i] = (up ? v[i + half] : v[i]) + other;
            }
        }
        v[0] += __shfl_xor_sync(0xffffffffu, v[0], 16);

        int row = base + r * 8 + w;
        if (lane < 16 && row < NN) {
            g_scores[so][(b * NN + row) * NH + ho] = v[0];
        }
    }
}

// ---------------------------------------------------------------------------
// K3: out[i] = sigmoid(scores_src[head[i]] + scores_trg[tail[i]])
// Index dtype resolved at runtime via g_idx_is64.
// ---------------------------------------------------------------------------
__global__ void k_gather(const void* __restrict__ head,
                         const void* __restrict__ tail,
                         float* __restrict__ out, int total) {
    int i = blockIdx.x * blockDim.x + threadIdx.x;
    if (i >= total) return;
    long long hi, ti;
    if (g_idx_is64) {
        hi = ((const long long*)head)[i];
        ti = ((const long long*)tail)[i];
    } else {
        hi = ((const int*)head)[i];
        ti = ((const int*)tail)[i];
    }
    float x = g_scores[0][hi] + g_scores[1][ti];
    out[i] = 1.f / (1.f + __expf(-x));
}

// ---------------------------------------------------------------------------
extern "C" void kernel_launch(void* const* d_in, const int* in_sizes, int n_in,
                              void* d_out, int out_size) {
    const float* ch   = (const float*)d_in[0];
    const void*  head = d_in[1];
    const void*  tail = d_in[2];
    const float* W    = (const float*)d_in[3];
    const float* src  = (const float*)d_in[4];
    const float* trg  = (const float*)d_in[5];
    float* out = (float*)d_out;

    k_sniff<<<1, 256>>>((const unsigned int*)head);
    k_prep<<<BSZ * 2 * NH, 256>>>(W, src, trg);

    dim3 g2((NN + ROWS_PER_BLOCK - 1) / ROWS_PER_BLOCK, BSZ);
    k_scores<<<g2, 256>>>(ch);

    int total = BSZ * EE;
    k_gather<<<(total + 255) / 256, 256>>>(head, tail, out, total);
}

// round 3
// speedup vs baseline: 1.0836x; 1.0836x over previous
#include <cuda_runtime.h>

#define BSZ   8
#define NN    20000
#define FIN   256
#define NH    8
#define ND    64
#define EE    160000

#define RPB   544        // rows per block (multiple of 128)
#define NBX   37         // ceil(20000/544)

typedef unsigned long long ull;

// Scratch (device globals — no allocation allowed)
__device__ float g_u[BSZ * 2 * NH * FIN];          // [b][s][h][f]  (o = s*8+h)
__device__ float g_scores[2][BSZ * NN * NH];       // [s][(b*N+n)*8+h]
__device__ int   g_idx_is64;

__device__ __forceinline__ void fma2(ull& d, ull a, ull b) {
    asm("fma.rn.f32x2 %0, %1, %2, %0;" : "+l"(d) : "l"(a), "l"(b));
}
__device__ __forceinline__ void upk2(ull v, float& lo, float& hi) {
    asm("mov.b64 {%0, %1}, %2;" : "=f"(lo), "=f"(hi) : "l"(v));
}

// ---------------------------------------------------------------------------
// K0: sniff index dtype (int64 -> odd 32-bit words all zero).
// ---------------------------------------------------------------------------
__global__ void k_sniff(const unsigned int* __restrict__ head_words) {
    __shared__ int any_nonzero;
    if (threadIdx.x == 0) any_nonzero = 0;
    __syncthreads();
    for (int i = threadIdx.x; i < 1024; i += blockDim.x)
        if (head_words[2 * i + 1] != 0u) any_nonzero = 1;
    __syncthreads();
    if (threadIdx.x == 0) g_idx_is64 = any_nonzero ? 0 : 1;
}

// ---------------------------------------------------------------------------
// K1: u[b][o][f] = sum_d W[h*64+d][f] * scoring_{s}[b][h][d],  o = s*8+h
// ---------------------------------------------------------------------------
__global__ void k_prep(const float* __restrict__ W,
                       const float* __restrict__ src,
                       const float* __restrict__ trg) {
    int blk = blockIdx.x;
    int h = blk & 7;
    int s = (blk >> 3) & 1;
    int b = blk >> 4;
    int f = threadIdx.x;

    __shared__ float sc[ND];
    const float* scp = (s == 0 ? src : trg) + (b * NH + h) * ND;
    if (threadIdx.x < ND) sc[threadIdx.x] = scp[threadIdx.x];
    __syncthreads();

    const float* Wp = W + (h * ND) * FIN + f;
    float acc = 0.f;
#pragma unroll 8
    for (int d = 0; d < ND; d++) acc = fmaf(Wp[d * FIN], sc[d], acc);
    g_u[((b * 2 + s) * NH + h) * FIN + f] = acc;
}

// ---------------------------------------------------------------------------
// K2: scores[(b,n,o)] = sum_f ch[b][n][f] * u[b][o][f]
//
// Lane layout: og = lane&3 (4 outs each), rl = (lane>>2)&3 (row slot),
//              fq = lane>>4 (f half, 128 each).
// Thread: 4 rows x 4 outs, acc = 16 packed f32x2.
// u table in smem (16KB), XOR-swizzled so every u LDS.128 is conflict-free.
// Reduction: single shfl_xor(16) across fq halves; STG.128 per (row, og).
// ---------------------------------------------------------------------------
__global__ void __launch_bounds__(256, 2)
k_scores(const float* __restrict__ ch) {
    __shared__ float4 u_s[16 * 64];
    const int b = blockIdx.y;

    // Load u[b] once per block, swizzled: idx = o*64 + fq*32 + (fi4 ^ (o>>2) ^ (fq<<2))
    for (int e = threadIdx.x; e < 1024; e += 256) {
        int o = e >> 6, f4 = e & 63;
        int fqf = f4 >> 5, fi4 = f4 & 31;
        float4 v = *(const float4*)(g_u + ((b * 16 + o) << 8) + (f4 << 2));
        u_s[(o << 6) + (fqf << 5) + (fi4 ^ (o >> 2) ^ (fqf << 2))] = v;
    }
    __syncthreads();

    const int w    = threadIdx.x >> 5;
    const int lane = threadIdx.x & 31;
    const int og   = lane & 3;
    const int rl   = (lane >> 2) & 3;
    const int fq   = lane >> 4;

    const int r0   = blockIdx.x * RPB;
    const int rend = (r0 + RPB < NN) ? r0 + RPB : NN;

    const float* chb = ch + (size_t)b * NN * FIN + fq * 128;
    const ulonglong2* us = (const ulonglong2*)u_s;

    // Per-out u base indices (in 16B units) and swizzle mask.
    const int mask = og ^ (fq << 2);
    int ub0 = (og * 4 + 0) * 64 + fq * 32;
    int ub1 = (og * 4 + 1) * 64 + fq * 32;
    int ub2 = (og * 4 + 2) * 64 + fq * 32;
    int ub3 = (og * 4 + 3) * 64 + fq * 32;

    for (int rowbase = r0 + w * 16; rowbase < rend; rowbase += 128) {
        int row0 = rowbase + 0 * 4 + rl;
        int row1 = rowbase + 1 * 4 + rl;
        int row2 = rowbase + 2 * 4 + rl;
        int row3 = rowbase + 3 * 4 + rl;
        const ulonglong2* p0 = (const ulonglong2*)(chb + (size_t)(row0 < NN ? row0 : NN - 1) * FIN);
        const ulonglong2* p1 = (const ulonglong2*)(chb + (size_t)(row1 < NN ? row1 : NN - 1) * FIN);
        const ulonglong2* p2 = (const ulonglong2*)(chb + (size_t)(row2 < NN ? row2 : NN - 1) * FIN);
        const ulonglong2* p3 = (const ulonglong2*)(chb + (size_t)(row3 < NN ? row3 : NN - 1) * FIN);

        ull acc[4][4];
#pragma unroll
        for (int j = 0; j < 4; j++)
#pragma unroll
            for (int i = 0; i < 4; i++) acc[j][i] = 0ull;

#pragma unroll 8
        for (int fi4 = 0; fi4 < 32; fi4++) {
            ulonglong2 c0 = p0[fi4];
            ulonglong2 c1 = p1[fi4];
            ulonglong2 c2 = p2[fi4];
            ulonglong2 c3 = p3[fi4];
            int sx = fi4 ^ mask;
            ulonglong2 u0 = us[ub0 + sx];
            ulonglong2 u1 = us[ub1 + sx];
            ulonglong2 u2 = us[ub2 + sx];
            ulonglong2 u3 = us[ub3 + sx];

            fma2(acc[0][0], c0.x, u0.x); fma2(acc[0][0], c0.y, u0.y);
            fma2(acc[0][1], c0.x, u1.x); fma2(acc[0][1], c0.y, u1.y);
            fma2(acc[0][2], c0.x, u2.x); fma2(acc[0][2], c0.y, u2.y);
            fma2(acc[0][3], c0.x, u3.x); fma2(acc[0][3], c0.y, u3.y);

            fma2(acc[1][0], c1.x, u0.x); fma2(acc[1][0], c1.y, u0.y);
            fma2(acc[1][1], c1.x, u1.x); fma2(acc[1][1], c1.y, u1.y);
            fma2(acc[1][2], c1.x, u2.x); fma2(acc[1][2], c1.y, u2.y);
            fma2(acc[1][3], c1.x, u3.x); fma2(acc[1][3], c1.y, u3.y);

            fma2(acc[2][0], c2.x, u0.x); fma2(acc[2][0], c2.y, u0.y);
            fma2(acc[2][1], c2.x, u1.x); fma2(acc[2][1], c2.y, u1.y);
            fma2(acc[2][2], c2.x, u2.x); fma2(acc[2][2], c2.y, u2.y);
            fma2(acc[2][3], c2.x, u3.x); fma2(acc[2][3], c2.y, u3.y);

            fma2(acc[3][0], c3.x, u0.x); fma2(acc[3][0], c3.y, u0.y);
            fma2(acc[3][1], c3.x, u1.x); fma2(acc[3][1], c3.y, u1.y);
            fma2(acc[3][2], c3.x, u2.x); fma2(acc[3][2], c3.y, u2.y);
            fma2(acc[3][3], c3.x, u3.x); fma2(acc[3][3], c3.y, u3.y);
        }

        // Epilogue: horizontal add + combine fq halves + store.
        const int s_tab = og >> 1;
        const int hoff  = (og & 1) * 4;
        int rows[4] = {row0, row1, row2, row3};
#pragma unroll
        for (int j = 0; j < 4; j++) {
            float v[4];
#pragma unroll
            for (int i = 0; i < 4; i++) {
                float lo, hi; upk2(acc[j][i], lo, hi);
                v[i] = lo + hi;
            }
#pragma unroll
            for (int i = 0; i < 4; i++)
                v[i] += __shfl_xor_sync(0xffffffffu, v[i], 16);
            if (fq == 0 && rows[j] < NN) {
                float4 o4 = make_float4(v[0], v[1], v[2], v[3]);
                *(float4*)&g_scores[s_tab][((size_t)b * NN + rows[j]) * NH + hoff] = o4;
            }
        }
    }
}

// ---------------------------------------------------------------------------
// K3: out[i] = sigmoid(scores_src[head[i]] + scores_trg[tail[i]])
// 4 edges per thread, vectorized index loads for MLP.
// ---------------------------------------------------------------------------
__global__ void k_gather(const void* __restrict__ head,
                         const void* __restrict__ tail,
                         float* __restrict__ out, int total) {
    int i = blockIdx.x * blockDim.x + threadIdx.x;   // edge group of 4
    int e0 = i * 4;
    if (e0 >= total) return;

    long long h[4], t[4];
    if (g_idx_is64) {
        longlong2 a0 = ((const longlong2*)head)[2 * i];
        longlong2 a1 = ((const longlong2*)head)[2 * i + 1];
        longlong2 b0 = ((const longlong2*)tail)[2 * i];
        longlong2 b1 = ((const longlong2*)tail)[2 * i + 1];
        h[0] = a0.x; h[1] = a0.y; h[2] = a1.x; h[3] = a1.y;
        t[0] = b0.x; t[1] = b0.y; t[2] = b1.x; t[3] = b1.y;
    } else {
        int4 a = ((const int4*)head)[i];
        int4 c = ((const int4*)tail)[i];
        h[0] = a.x; h[1] = a.y; h[2] = a.z; h[3] = a.w;
        t[0] = c.x; t[1] = c.y; t[2] = c.z; t[3] = c.w;
    }

    float x[4];
#pragma unroll
    for (int k = 0; k < 4; k++)
        x[k] = g_scores[0][h[k]] + g_scores[1][t[k]];

    float4 r;
    r.x = 1.f / (1.f + __expf(-x[0]));
    r.y = 1.f / (1.f + __expf(-x[1]));
    r.z = 1.f / (1.f + __expf(-x[2]));
    r.w = 1.f / (1.f + __expf(-x[3]));
    ((float4*)out)[i] = r;
}

// ---------------------------------------------------------------------------
extern "C" void kernel_launch(void* const* d_in, const int* in_sizes, int n_in,
                              void* d_out, int out_size) {
    const float* ch   = (const float*)d_in[0];
    const void*  head = d_in[1];
    const void*  tail = d_in[2];
    const float* W    = (const float*)d_in[3];
    const float* src  = (const float*)d_in[4];
    const float* trg  = (const float*)d_in[5];
    float* out = (float*)d_out;

    k_sniff<<<1, 256>>>((const unsigned int*)head);
    k_prep<<<BSZ * 2 * NH, 256>>>(W, src, trg);

    dim3 g2(NBX, BSZ);
    k_scores<<<g2, 256>>>(ch);

    int total = BSZ * EE;                       // 1,280,000 (multiple of 4)
    int groups = total / 4;
    k_gather<<<(groups + 255) / 256, 256>>>(head, tail, out, total);
}